// round 3
// baseline (speedup 1.0000x reference)
#include <cuda_runtime.h>
#include <cstdint>

#define N_NODES 100000
#define N_EDGES 1600000
#define D 128

// Scratch: aggregation buffer (51.2 MB) + index-width flag. Device globals (no allocation).
__device__ float g_agg[(size_t)N_NODES * D];
__device__ int g_idx64;

// ---------------------------------------------------------------------------
// Detect whether index arrays are int64 or int32.
// If the buffer really holds int64 indices, every 8-byte value is in [0, N).
// If it holds int32 indices, an 8-byte read combines two random indices; the
// high word is nonzero with prob ~0.99999 per entry -> 128 entries all "valid"
// is impossible in practice.
// ---------------------------------------------------------------------------
__global__ void detect_idx_kernel(const void* __restrict__ src_raw) {
    const long long* p = (const long long*)src_raw;
    int ok = 1;
    for (int i = 0; i < 128; i++) {
        long long v = p[i];
        if (v < 0 || v >= N_NODES) { ok = 0; break; }
    }
    g_idx64 = ok;
}

// ---------------------------------------------------------------------------
// Zero the aggregation buffer (float4 stores).
// ---------------------------------------------------------------------------
__global__ void zero_agg_kernel() {
    int i = blockIdx.x * blockDim.x + threadIdx.x;
    const int n4 = N_NODES * D / 4;
    if (i < n4) {
        ((float4*)g_agg)[i] = make_float4(0.f, 0.f, 0.f, 0.f);
    }
}

// ---------------------------------------------------------------------------
// Edge scatter: 32 threads per edge, each thread moves one float4.
// agg[dst[e]] += x[src[e]] via red.global.add.v4.f32 (L2-native vector atomic).
// ---------------------------------------------------------------------------
__global__ __launch_bounds__(256) void scatter_kernel(
    const float* __restrict__ x,
    const void* __restrict__ src_raw,
    const void* __restrict__ dst_raw)
{
    long long gid = (long long)blockIdx.x * blockDim.x + threadIdx.x;
    int e  = (int)(gid >> 5);
    int ln = (int)(gid & 31);
    if (e >= N_EDGES) return;

    int s, d;
    if (g_idx64) {
        s = (int)((const long long*)src_raw)[e];
        d = (int)((const long long*)dst_raw)[e];
    } else {
        s = ((const int*)src_raw)[e];
        d = ((const int*)dst_raw)[e];
    }

    float4 v = *(const float4*)(x + (size_t)s * D + ln * 4);
    float* out = g_agg + (size_t)d * D + ln * 4;
    asm volatile("red.global.add.v4.f32 [%0], {%1,%2,%3,%4};"
                 :: "l"(out), "f"(v.x), "f"(v.y), "f"(v.z), "f"(v.w)
                 : "memory");
}

// ---------------------------------------------------------------------------
// Dense GEMM + bias: out[n][o] = sum_i agg[n][i] * W[o][i] + b[o]
// One warp per row. W is staged transposed in smem (Wt[i][o]) so each lane
// reads a conflict-free float4 of 4 output columns; the agg row is held in
// registers and broadcast via shfl.
// ---------------------------------------------------------------------------
#define GEMM_BLOCKS 444
#define GEMM_THREADS 256

__global__ __launch_bounds__(GEMM_THREADS) void gemm_kernel(
    const float* __restrict__ W,
    const float* __restrict__ b,
    float* __restrict__ out)
{
    extern __shared__ float smem[];
    float* Wt = smem;            // [D][D], Wt[i*D + o] = W[o*D + i]  (64 KB)
    float* bs = smem + D * D;    // [D]

    int tid = threadIdx.x;
    for (int idx = tid; idx < D * D; idx += GEMM_THREADS) {
        int o = idx / D, i = idx % D;
        Wt[i * D + o] = W[idx];
    }
    if (tid < D) bs[tid] = b[tid];
    __syncthreads();

    int warp = tid >> 5;
    int ln   = tid & 31;
    const int warps_total = GEMM_BLOCKS * (GEMM_THREADS / 32);

    for (int row = blockIdx.x * (GEMM_THREADS / 32) + warp;
         row < N_NODES;
         row += warps_total)
    {
        // Row of agg held across the warp: lane ln owns elements [ln*4, ln*4+4)
        float4 r = *(const float4*)(g_agg + (size_t)row * D + ln * 4);
        // Each lane computes output columns [ln*4, ln*4+4)
        float4 acc = *(const float4*)(bs + ln * 4);

        #pragma unroll
        for (int j = 0; j < 4; j++) {
            float rj = (j == 0) ? r.x : (j == 1) ? r.y : (j == 2) ? r.z : r.w;
            #pragma unroll
            for (int sl = 0; sl < 32; sl++) {
                float a = __shfl_sync(0xffffffffu, rj, sl);
                int i = sl * 4 + j;
                float4 w = *(const float4*)(Wt + i * D + ln * 4);
                acc.x += a * w.x;
                acc.y += a * w.y;
                acc.z += a * w.z;
                acc.w += a * w.w;
            }
        }

        *(float4*)(out + (size_t)row * D + ln * 4) = acc;
    }
}

// ---------------------------------------------------------------------------
// Launch
// ---------------------------------------------------------------------------
extern "C" void kernel_launch(void* const* d_in, const int* in_sizes, int n_in,
                              void* d_out, int out_size) {
    const float* x   = (const float*)d_in[0];
    const void*  src = d_in[1];
    const void*  dst = d_in[2];
    const float* W   = (const float*)d_in[3];
    const float* b   = (const float*)d_in[4];
    float* out = (float*)d_out;

    static int smem_set = 0;
    if (!smem_set) {
        cudaFuncSetAttribute(gemm_kernel,
                             cudaFuncAttributeMaxDynamicSharedMemorySize,
                             (D * D + D) * (int)sizeof(float));
        smem_set = 1;
    }

    detect_idx_kernel<<<1, 1>>>(src);

    {
        int n4 = N_NODES * D / 4;
        zero_agg_kernel<<<(n4 + 255) / 256, 256>>>();
    }

    {
        long long total = (long long)N_EDGES * 32;
        int blocks = (int)((total + 255) / 256);
        scatter_kernel<<<blocks, 256>>>(x, src, dst);
    }

    gemm_kernel<<<GEMM_BLOCKS, GEMM_THREADS,
                  (D * D + D) * (int)sizeof(float)>>>(W, b, out);
}

// round 4
// speedup vs baseline: 1.3046x; 1.3046x over previous
#include <cuda_runtime.h>
#include <cstdint>

#define N_NODES 100000
#define N_EDGES 1600000
#define D 128

// Scratch: aggregation buffer (51.2 MB) + index-width flag. Device globals (no allocation).
__device__ float g_agg[(size_t)N_NODES * D];
__device__ int g_idx64;

// ---------------------------------------------------------------------------
// Detect whether index arrays are int64 or int32 (see round 0 rationale).
// ---------------------------------------------------------------------------
__global__ void detect_idx_kernel(const void* __restrict__ src_raw) {
    const long long* p = (const long long*)src_raw;
    int ok = 1;
    for (int i = 0; i < 128; i++) {
        long long v = p[i];
        if (v < 0 || v >= N_NODES) { ok = 0; break; }
    }
    g_idx64 = ok;
}

// ---------------------------------------------------------------------------
// Zero the aggregation buffer (float4 stores).
// ---------------------------------------------------------------------------
__global__ void zero_agg_kernel() {
    int i = blockIdx.x * blockDim.x + threadIdx.x;
    const int n4 = N_NODES * D / 4;
    if (i < n4) {
        ((float4*)g_agg)[i] = make_float4(0.f, 0.f, 0.f, 0.f);
    }
}

// ---------------------------------------------------------------------------
// Edge scatter: 32 threads per edge, each thread moves one float4.
// agg[dst[e]] += x[src[e]] via red.global.add.v4.f32 (L2-native vector atomic).
// ---------------------------------------------------------------------------
__global__ __launch_bounds__(256) void scatter_kernel(
    const float* __restrict__ x,
    const void* __restrict__ src_raw,
    const void* __restrict__ dst_raw)
{
    long long gid = (long long)blockIdx.x * blockDim.x + threadIdx.x;
    int e  = (int)(gid >> 5);
    int ln = (int)(gid & 31);
    if (e >= N_EDGES) return;

    int s, d;
    if (g_idx64) {
        s = (int)((const long long*)src_raw)[e];
        d = (int)((const long long*)dst_raw)[e];
    } else {
        s = ((const int*)src_raw)[e];
        d = ((const int*)dst_raw)[e];
    }

    float4 v = *(const float4*)(x + (size_t)s * D + ln * 4);
    float* out = g_agg + (size_t)d * D + ln * 4;
    asm volatile("red.global.add.v4.f32 [%0], {%1,%2,%3,%4};"
                 :: "l"(out), "f"(v.x), "f"(v.y), "f"(v.z), "f"(v.w)
                 : "memory");
}

// ---------------------------------------------------------------------------
// Tiled SGEMM + bias using packed fp32x2 FMA (Blackwell).
// out[n][o] = sum_i agg[n][i] * W[o][i] + b[o]
// 128x128 block tile, 256 threads, 8x8 micro-tile per thread.
// A (agg tile) row-major in smem, read as 2-address broadcasts.
// W transposed once per block into Wt[k][o] (pad 130 for alignment).
// Accumulators are 32 x u64 (f32x2 pairs over adjacent output columns).
// ---------------------------------------------------------------------------
#define PKW 130
#define GEMM_THREADS 256
#define GEMM_BLOCKS ((N_NODES + 127) / 128)

__device__ __forceinline__ unsigned long long pack2(float a) {
    unsigned long long r;
    asm("mov.b64 %0, {%1, %1};" : "=l"(r) : "f"(a));
    return r;
}
__device__ __forceinline__ unsigned long long fma2(unsigned long long a,
                                                   unsigned long long b,
                                                   unsigned long long c) {
    unsigned long long d;
    asm("fma.rn.f32x2 %0, %1, %2, %3;" : "=l"(d) : "l"(a), "l"(b), "l"(c));
    return d;
}

__global__ __launch_bounds__(GEMM_THREADS) void gemm_kernel(
    const float* __restrict__ W,
    const float* __restrict__ b,
    float* __restrict__ out)
{
    extern __shared__ float smem[];
    float* As = smem;                    // [128][128]
    float* Wt = smem + 128 * 128;        // [128][PKW], Wt[k*PKW + o] = W[o][k]
    float* bs = Wt + 128 * PKW;          // [128]

    const int tid = threadIdx.x;
    const int rb  = blockIdx.x * 128;

    // Load A tile (guard tail rows), coalesced float4, conflict-free STS.
    for (int i = tid; i < 128 * 32; i += GEMM_THREADS) {
        int r = i >> 5, c4 = i & 31;
        float4 v = make_float4(0.f, 0.f, 0.f, 0.f);
        int grow = rb + r;
        if (grow < N_NODES)
            v = *(const float4*)(g_agg + (size_t)grow * D + c4 * 4);
        *(float4*)(As + r * 128 + c4 * 4) = v;
    }
    // Load + transpose W: Wt[k][o] = W[o][k].
    for (int i = tid; i < 128 * 32; i += GEMM_THREADS) {
        int o = i >> 5, i4 = i & 31;
        float4 v = *(const float4*)(W + o * 128 + i4 * 4);
        Wt[(i4 * 4 + 0) * PKW + o] = v.x;
        Wt[(i4 * 4 + 1) * PKW + o] = v.y;
        Wt[(i4 * 4 + 2) * PKW + o] = v.z;
        Wt[(i4 * 4 + 3) * PKW + o] = v.w;
    }
    if (tid < 128) bs[tid] = b[tid];
    __syncthreads();

    const int tx = tid & 15, ty = tid >> 4;
    const int r0 = ty * 8;           // micro-tile rows (within block)
    const int c0 = tx * 8;           // micro-tile cols

    // Init accumulators from bias (pairs of adjacent columns).
    unsigned long long acc[8][4];
    {
        const unsigned long long* bp = (const unsigned long long*)(bs + c0);
        unsigned long long b0 = bp[0], b1 = bp[1], b2 = bp[2], b3 = bp[3];
        #pragma unroll
        for (int i = 0; i < 8; i++) {
            acc[i][0] = b0; acc[i][1] = b1; acc[i][2] = b2; acc[i][3] = b3;
        }
    }

    #pragma unroll 8
    for (int k = 0; k < 128; k++) {
        // W row: 4 x LDS.64, 16 distinct consecutive 8B addrs -> conflict-free.
        const unsigned long long* wp =
            (const unsigned long long*)(Wt + k * PKW + c0);
        unsigned long long w0 = wp[0], w1 = wp[1], w2 = wp[2], w3 = wp[3];

        // A values: scalar broadcast reads (2 addresses per warp).
        unsigned long long a2[8];
        #pragma unroll
        for (int i = 0; i < 8; i++)
            a2[i] = pack2(As[(r0 + i) * 128 + k]);

        #pragma unroll
        for (int i = 0; i < 8; i++) {
            acc[i][0] = fma2(a2[i], w0, acc[i][0]);
            acc[i][1] = fma2(a2[i], w1, acc[i][1]);
            acc[i][2] = fma2(a2[i], w2, acc[i][2]);
            acc[i][3] = fma2(a2[i], w3, acc[i][3]);
        }
    }

    // Store micro-tile (little-endian f32x2 pairs == adjacent columns).
    #pragma unroll
    for (int i = 0; i < 8; i++) {
        int grow = rb + r0 + i;
        if (grow < N_NODES) {
            ulonglong2* dst = (ulonglong2*)(out + (size_t)grow * D + c0);
            dst[0] = make_ulonglong2(acc[i][0], acc[i][1]);
            dst[1] = make_ulonglong2(acc[i][2], acc[i][3]);
        }
    }
}

// ---------------------------------------------------------------------------
// Launch
// ---------------------------------------------------------------------------
extern "C" void kernel_launch(void* const* d_in, const int* in_sizes, int n_in,
                              void* d_out, int out_size) {
    const float* x   = (const float*)d_in[0];
    const void*  src = d_in[1];
    const void*  dst = d_in[2];
    const float* W   = (const float*)d_in[3];
    const float* b   = (const float*)d_in[4];
    float* out = (float*)d_out;

    const int gemm_smem = (128 * 128 + 128 * PKW + 128) * (int)sizeof(float);

    static int smem_set = 0;
    if (!smem_set) {
        cudaFuncSetAttribute(gemm_kernel,
                             cudaFuncAttributeMaxDynamicSharedMemorySize,
                             gemm_smem);
        smem_set = 1;
    }

    detect_idx_kernel<<<1, 1>>>(src);

    {
        int n4 = N_NODES * D / 4;
        zero_agg_kernel<<<(n4 + 255) / 256, 256>>>();
    }

    {
        long long total = (long long)N_EDGES * 32;
        int blocks = (int)((total + 255) / 256);
        scatter_kernel<<<blocks, 256>>>(x, src, dst);
    }

    gemm_kernel<<<GEMM_BLOCKS, GEMM_THREADS, gemm_smem>>>(W, b, out);
}

// round 5
// speedup vs baseline: 2.3634x; 1.8116x over previous
#include <cuda_runtime.h>
#include <cstdint>

#define N_NODES 100000
#define N_EDGES 1600000
#define D 128

// ---------------------------------------------------------------------------
// Scratch (device globals; no allocation allowed).
// ---------------------------------------------------------------------------
__device__ float g_agg[(size_t)N_NODES * D];     // aggregated features
__device__ float g_Wt[D * D];                    // W transposed: g_Wt[k*D+o] = W[o][k]
__device__ int   g_deg[N_NODES];
__device__ int   g_row[N_NODES + 1];
__device__ int   g_cursor[N_NODES];
__device__ int   g_bsum[512];
__device__ int   g_csr[N_EDGES];                 // src node ids grouped by dst
__device__ int   g_idx64;

// ---------------------------------------------------------------------------
// Detect whether index arrays are int64 or int32 (see round 0 rationale).
// ---------------------------------------------------------------------------
__global__ void detect_idx_kernel(const void* __restrict__ src_raw) {
    const long long* p = (const long long*)src_raw;
    int ok = 1;
    for (int i = 0; i < 128; i++) {
        long long v = p[i];
        if (v < 0 || v >= N_NODES) { ok = 0; break; }
    }
    g_idx64 = ok;
}

__device__ __forceinline__ int load_idx(const void* raw, int e) {
    return g_idx64 ? (int)((const long long*)raw)[e] : ((const int*)raw)[e];
}

// ---------------------------------------------------------------------------
// One-time W transpose into global (coalesced smem-free version; 64KB total).
// ---------------------------------------------------------------------------
__global__ void prep_w_kernel(const float* __restrict__ W) {
    int k = blockIdx.x;
    for (int o = threadIdx.x; o < D; o += blockDim.x)
        g_Wt[k * D + o] = W[o * D + k];
}

// ---------------------------------------------------------------------------
// CSR build: zero degrees -> histogram -> scan (3 kernels) -> fill.
// ---------------------------------------------------------------------------
__global__ void zero_deg_kernel() {
    int i = blockIdx.x * blockDim.x + threadIdx.x;
    if (i < N_NODES) g_deg[i] = 0;
}

__global__ void hist_kernel(const void* __restrict__ dst_raw) {
    int e = blockIdx.x * blockDim.x + threadIdx.x;
    if (e < N_EDGES) atomicAdd(&g_deg[load_idx(dst_raw, e)], 1);
}

#define SCAN_B 512
__global__ void scan1_kernel() {       // grid 196, block 512
    __shared__ int s[SCAN_B];
    int gid = blockIdx.x * SCAN_B + threadIdx.x;
    int v = (gid < N_NODES) ? g_deg[gid] : 0;
    s[threadIdx.x] = v;
    __syncthreads();
    for (int off = 1; off < SCAN_B; off <<= 1) {
        int t = (threadIdx.x >= off) ? s[threadIdx.x - off] : 0;
        __syncthreads();
        s[threadIdx.x] += t;
        __syncthreads();
    }
    if (gid < N_NODES) g_row[gid] = s[threadIdx.x] - v;   // exclusive within block
    if (threadIdx.x == SCAN_B - 1) g_bsum[blockIdx.x] = s[SCAN_B - 1];
}

__global__ void scan2_kernel(int nblocks) {   // 1 block, 512 threads
    __shared__ int s[SCAN_B];
    int v = (threadIdx.x < nblocks) ? g_bsum[threadIdx.x] : 0;
    s[threadIdx.x] = v;
    __syncthreads();
    for (int off = 1; off < SCAN_B; off <<= 1) {
        int t = (threadIdx.x >= off) ? s[threadIdx.x - off] : 0;
        __syncthreads();
        s[threadIdx.x] += t;
        __syncthreads();
    }
    g_bsum[threadIdx.x] = s[threadIdx.x] - v;             // exclusive block offsets
}

__global__ void scan3_kernel() {
    int gid = blockIdx.x * blockDim.x + threadIdx.x;
    if (gid < N_NODES) {
        int r = g_row[gid] + g_bsum[gid >> 9];
        g_row[gid] = r;
        g_cursor[gid] = r;
    }
    if (gid == 0) g_row[N_NODES] = N_EDGES;
}

__global__ void fill_kernel(const void* __restrict__ src_raw,
                            const void* __restrict__ dst_raw) {
    int e = blockIdx.x * blockDim.x + threadIdx.x;
    if (e >= N_EDGES) return;
    int d = load_idx(dst_raw, e);
    int s = load_idx(src_raw, e);
    int p = atomicAdd(&g_cursor[d], 1);
    g_csr[p] = s;
}

// ---------------------------------------------------------------------------
// Gather aggregation: one warp per node; lane owns one float4 column chunk.
// Pure reads, no atomics; unroll-4 for MLP.
// ---------------------------------------------------------------------------
__global__ __launch_bounds__(256) void gather_kernel(const float* __restrict__ x) {
    int wid = threadIdx.x >> 5;
    int ln  = threadIdx.x & 31;
    int node = blockIdx.x * 8 + wid;
    if (node >= N_NODES) return;

    int beg = g_row[node];
    int end = g_row[node + 1];

    const float4* xv = (const float4*)x;
    float4 acc = make_float4(0.f, 0.f, 0.f, 0.f);

    int j = beg;
    for (; j + 4 <= end; j += 4) {
        int s0 = g_csr[j], s1 = g_csr[j + 1], s2 = g_csr[j + 2], s3 = g_csr[j + 3];
        float4 v0 = xv[(size_t)s0 * 32 + ln];
        float4 v1 = xv[(size_t)s1 * 32 + ln];
        float4 v2 = xv[(size_t)s2 * 32 + ln];
        float4 v3 = xv[(size_t)s3 * 32 + ln];
        acc.x += (v0.x + v1.x) + (v2.x + v3.x);
        acc.y += (v0.y + v1.y) + (v2.y + v3.y);
        acc.z += (v0.z + v1.z) + (v2.z + v3.z);
        acc.w += (v0.w + v1.w) + (v2.w + v3.w);
    }
    for (; j < end; j++) {
        float4 v = xv[(size_t)g_csr[j] * 32 + ln];
        acc.x += v.x; acc.y += v.y; acc.z += v.z; acc.w += v.w;
    }

    *(float4*)(g_agg + (size_t)node * D + ln * 4) = acc;
}

// ---------------------------------------------------------------------------
// Tiled SGEMM + bias, f32x2 FMAs, conflict-free shared accesses.
// 64x128 block tile, 256 threads, 4x8 micro-tile.
// Thread (tx=tid&15, ty=tid>>4): rows rb+4ty..+3, cols {2tx+32g, +1} g=0..3.
//  - W loads: LDS.64 at byte 8*tx+128g -> 16 consecutive 8B addrs, conflict-free
//    (lanes 16-31 duplicate lanes 0-15 -> broadcast).
//  - A loads: 2 distinct broadcast addresses per warp; As stride 132 puts the
//    two ty rows on different banks.
// smem = 64*132*4 + 64KB + 512 = ~98.4KB -> 2 CTAs/SM.
// ---------------------------------------------------------------------------
#define AS_STRIDE 132
#define GEMM_THREADS 256
#define GEMM_BLOCKS ((N_NODES + 63) / 64)

__device__ __forceinline__ unsigned long long pack2(float a) {
    unsigned long long r;
    asm("mov.b64 %0, {%1, %1};" : "=l"(r) : "f"(a));
    return r;
}
__device__ __forceinline__ unsigned long long fma2(unsigned long long a,
                                                   unsigned long long b,
                                                   unsigned long long c) {
    unsigned long long d;
    asm("fma.rn.f32x2 %0, %1, %2, %3;" : "=l"(d) : "l"(a), "l"(b), "l"(c));
    return d;
}

__global__ __launch_bounds__(GEMM_THREADS) void gemm_kernel(
    const float* __restrict__ b,
    float* __restrict__ out)
{
    extern __shared__ float smem[];
    float* As = smem;                       // [64][AS_STRIDE]
    float* Wt = smem + 64 * AS_STRIDE;      // [128][128] (k-major)
    float* bs = Wt + D * D;                 // [128]

    const int tid = threadIdx.x;
    const int rb  = blockIdx.x * 64;

    // A tile: coalesced float4 loads, 16B-aligned stores (AS_STRIDE*4 % 16 == 0).
    for (int i = tid; i < 64 * 32; i += GEMM_THREADS) {
        int r = i >> 5, c4 = i & 31;
        float4 v = make_float4(0.f, 0.f, 0.f, 0.f);
        int grow = rb + r;
        if (grow < N_NODES)
            v = *(const float4*)(g_agg + (size_t)grow * D + c4 * 4);
        *(float4*)(As + r * AS_STRIDE + c4 * 4) = v;
    }
    // W tile: already transposed in global -> straight coalesced copy.
    for (int i = tid; i < 128 * 32; i += GEMM_THREADS) {
        int k = i >> 5, c4 = i & 31;
        *(float4*)(Wt + k * D + c4 * 4) = *(const float4*)(g_Wt + k * D + c4 * 4);
    }
    if (tid < D) bs[tid] = b[tid];
    __syncthreads();

    const int tx = tid & 15, ty = tid >> 4;
    const int r0 = ty * 4;

    unsigned long long acc[4][4];
    {
        const unsigned long long* bp = (const unsigned long long*)bs;
        #pragma unroll
        for (int g = 0; g < 4; g++) {
            unsigned long long bv = bp[tx + 16 * g];
            #pragma unroll
            for (int i = 0; i < 4; i++) acc[i][g] = bv;
        }
    }

    #pragma unroll 8
    for (int k = 0; k < 128; k++) {
        const unsigned long long* wp = (const unsigned long long*)(Wt + k * D);
        unsigned long long w0 = wp[tx];
        unsigned long long w1 = wp[tx + 16];
        unsigned long long w2 = wp[tx + 32];
        unsigned long long w3 = wp[tx + 48];

        unsigned long long a2[4];
        #pragma unroll
        for (int i = 0; i < 4; i++)
            a2[i] = pack2(As[(r0 + i) * AS_STRIDE + k]);

        #pragma unroll
        for (int i = 0; i < 4; i++) {
            acc[i][0] = fma2(a2[i], w0, acc[i][0]);
            acc[i][1] = fma2(a2[i], w1, acc[i][1]);
            acc[i][2] = fma2(a2[i], w2, acc[i][2]);
            acc[i][3] = fma2(a2[i], w3, acc[i][3]);
        }
    }

    #pragma unroll
    for (int i = 0; i < 4; i++) {
        int grow = rb + r0 + i;
        if (grow < N_NODES) {
            unsigned long long* dst =
                (unsigned long long*)(out + (size_t)grow * D + 2 * tx);
            dst[0]  = acc[i][0];
            dst[16] = acc[i][1];
            dst[32] = acc[i][2];
            dst[48] = acc[i][3];
        }
    }
}

// ---------------------------------------------------------------------------
// Launch
// ---------------------------------------------------------------------------
extern "C" void kernel_launch(void* const* d_in, const int* in_sizes, int n_in,
                              void* d_out, int out_size) {
    const float* x   = (const float*)d_in[0];
    const void*  src = d_in[1];
    const void*  dst = d_in[2];
    const float* W   = (const float*)d_in[3];
    const float* b   = (const float*)d_in[4];
    float* out = (float*)d_out;

    const int gemm_smem = (64 * AS_STRIDE + D * D + D) * (int)sizeof(float);

    static int smem_set = 0;
    if (!smem_set) {
        cudaFuncSetAttribute(gemm_kernel,
                             cudaFuncAttributeMaxDynamicSharedMemorySize,
                             gemm_smem);
        smem_set = 1;
    }

    const int scan_blocks = (N_NODES + SCAN_B - 1) / SCAN_B;  // 196

    detect_idx_kernel<<<1, 1>>>(src);
    prep_w_kernel<<<D, 128>>>(W);

    zero_deg_kernel<<<(N_NODES + 255) / 256, 256>>>();
    hist_kernel<<<(N_EDGES + 255) / 256, 256>>>(dst);
    scan1_kernel<<<scan_blocks, SCAN_B>>>();
    scan2_kernel<<<1, SCAN_B>>>(scan_blocks);
    scan3_kernel<<<(N_NODES + 255) / 256, 256>>>();
    fill_kernel<<<(N_EDGES + 255) / 256, 256>>>(src, dst);

    gather_kernel<<<(N_NODES + 7) / 8, 256>>>(x);

    gemm_kernel<<<GEMM_BLOCKS, GEMM_THREADS, gemm_smem>>>(b, out);
}

// round 6
// speedup vs baseline: 2.3766x; 1.0056x over previous
#include <cuda_runtime.h>
#include <cstdint>

#define N_NODES 100000
#define N_EDGES 1600000
#define D 128

// ---------------------------------------------------------------------------
// Scratch (device globals; no allocation allowed).
// ---------------------------------------------------------------------------
__device__ float g_agg[(size_t)N_NODES * D];     // aggregated features
__device__ float g_Wt[D * D];                    // W transposed: g_Wt[k*D+o] = W[o][k]
__device__ int   g_deg[N_NODES];
__device__ int   g_row[N_NODES + 1];
__device__ int   g_cursor[N_NODES];
__device__ int   g_bsum[512];
__device__ int   g_csr[N_EDGES];                 // src node ids grouped by dst
__device__ int   g_idx64;

// ---------------------------------------------------------------------------
// Detect whether index arrays are int64 or int32 (see round 0 rationale).
// ---------------------------------------------------------------------------
__global__ void detect_idx_kernel(const void* __restrict__ src_raw) {
    const long long* p = (const long long*)src_raw;
    int ok = 1;
    for (int i = 0; i < 128; i++) {
        long long v = p[i];
        if (v < 0 || v >= N_NODES) { ok = 0; break; }
    }
    g_idx64 = ok;
}

// ---------------------------------------------------------------------------
// One-time W transpose into global.
// ---------------------------------------------------------------------------
__global__ void prep_w_kernel(const float* __restrict__ W) {
    int k = blockIdx.x;
    for (int o = threadIdx.x; o < D; o += blockDim.x)
        g_Wt[k * D + o] = W[o * D + k];
}

// ---------------------------------------------------------------------------
// Vectorized index fetch: 4 consecutive edges starting at 4*t.
// ---------------------------------------------------------------------------
__device__ __forceinline__ void load_idx4(const void* raw, int t, int idx[4]) {
    if (g_idx64) {
        longlong2 a = ((const longlong2*)raw)[2 * t];
        longlong2 b = ((const longlong2*)raw)[2 * t + 1];
        idx[0] = (int)a.x; idx[1] = (int)a.y;
        idx[2] = (int)b.x; idx[3] = (int)b.y;
    } else {
        int4 v = ((const int4*)raw)[t];
        idx[0] = v.x; idx[1] = v.y; idx[2] = v.z; idx[3] = v.w;
    }
}

// ---------------------------------------------------------------------------
// CSR build: histogram (4 edges/thread) -> scan (3 kernels) -> fill (4/thread).
// g_deg is zeroed by cudaMemsetAsync before hist.
// ---------------------------------------------------------------------------
__global__ __launch_bounds__(256) void hist_kernel(const void* __restrict__ dst_raw) {
    int t = blockIdx.x * blockDim.x + threadIdx.x;
    if (t >= N_EDGES / 4) return;
    int d[4];
    load_idx4(dst_raw, t, d);
    atomicAdd(&g_deg[d[0]], 1);
    atomicAdd(&g_deg[d[1]], 1);
    atomicAdd(&g_deg[d[2]], 1);
    atomicAdd(&g_deg[d[3]], 1);
}

#define SCAN_B 512
__global__ void scan1_kernel() {       // grid 196, block 512
    __shared__ int s[SCAN_B];
    int gid = blockIdx.x * SCAN_B + threadIdx.x;
    int v = (gid < N_NODES) ? g_deg[gid] : 0;
    s[threadIdx.x] = v;
    __syncthreads();
    for (int off = 1; off < SCAN_B; off <<= 1) {
        int t = (threadIdx.x >= off) ? s[threadIdx.x - off] : 0;
        __syncthreads();
        s[threadIdx.x] += t;
        __syncthreads();
    }
    if (gid < N_NODES) g_row[gid] = s[threadIdx.x] - v;   // exclusive within block
    if (threadIdx.x == SCAN_B - 1) g_bsum[blockIdx.x] = s[SCAN_B - 1];
}

__global__ void scan2_kernel(int nblocks) {   // 1 block, 512 threads
    __shared__ int s[SCAN_B];
    int v = (threadIdx.x < nblocks) ? g_bsum[threadIdx.x] : 0;
    s[threadIdx.x] = v;
    __syncthreads();
    for (int off = 1; off < SCAN_B; off <<= 1) {
        int t = (threadIdx.x >= off) ? s[threadIdx.x - off] : 0;
        __syncthreads();
        s[threadIdx.x] += t;
        __syncthreads();
    }
    g_bsum[threadIdx.x] = s[threadIdx.x] - v;             // exclusive block offsets
}

__global__ void scan3_kernel() {
    int gid = blockIdx.x * blockDim.x + threadIdx.x;
    if (gid < N_NODES) {
        int r = g_row[gid] + g_bsum[gid >> 9];
        g_row[gid] = r;
        g_cursor[gid] = r;
    }
    if (gid == 0) g_row[N_NODES] = N_EDGES;
}

__global__ __launch_bounds__(256) void fill_kernel(const void* __restrict__ src_raw,
                                                   const void* __restrict__ dst_raw) {
    int t = blockIdx.x * blockDim.x + threadIdx.x;
    if (t >= N_EDGES / 4) return;
    int d[4], s[4];
    load_idx4(dst_raw, t, d);
    load_idx4(src_raw, t, s);
    #pragma unroll
    for (int i = 0; i < 4; i++) {
        int p = atomicAdd(&g_cursor[d[i]], 1);
        g_csr[p] = s[i];
    }
}

// ---------------------------------------------------------------------------
// Gather aggregation: one warp per node; lane owns one float4 column chunk.
// Pure reads, no atomics; unroll-8 for MLP (avg degree = 16).
// ---------------------------------------------------------------------------
__global__ __launch_bounds__(256) void gather_kernel(const float* __restrict__ x) {
    int wid = threadIdx.x >> 5;
    int ln  = threadIdx.x & 31;
    int node = blockIdx.x * 8 + wid;
    if (node >= N_NODES) return;

    int beg = g_row[node];
    int end = g_row[node + 1];

    const float4* __restrict__ xv = (const float4*)x;
    float4 acc = make_float4(0.f, 0.f, 0.f, 0.f);

    int j = beg;
    for (; j + 8 <= end; j += 8) {
        int s[8];
        #pragma unroll
        for (int u = 0; u < 8; u++) s[u] = g_csr[j + u];
        float4 v[8];
        #pragma unroll
        for (int u = 0; u < 8; u++) v[u] = xv[(size_t)s[u] * 32 + ln];
        #pragma unroll
        for (int u = 0; u < 8; u++) {
            acc.x += v[u].x; acc.y += v[u].y;
            acc.z += v[u].z; acc.w += v[u].w;
        }
    }
    for (; j < end; j++) {
        float4 v = xv[(size_t)g_csr[j] * 32 + ln];
        acc.x += v.x; acc.y += v.y; acc.z += v.z; acc.w += v.w;
    }

    *(float4*)(g_agg + (size_t)node * D + ln * 4) = acc;
}

// ---------------------------------------------------------------------------
// Tiled SGEMM + bias, f32x2 FMAs, conflict-free shared accesses.
// 64x128 block tile, 256 threads, 4x8 micro-tile (see round-4 notes).
// smem ~= 98.4KB -> 2 CTAs/SM.
// ---------------------------------------------------------------------------
#define AS_STRIDE 132
#define GEMM_THREADS 256
#define GEMM_BLOCKS ((N_NODES + 63) / 64)

__device__ __forceinline__ unsigned long long pack2(float a) {
    unsigned long long r;
    asm("mov.b64 %0, {%1, %1};" : "=l"(r) : "f"(a));
    return r;
}
__device__ __forceinline__ unsigned long long fma2(unsigned long long a,
                                                   unsigned long long b,
                                                   unsigned long long c) {
    unsigned long long d;
    asm("fma.rn.f32x2 %0, %1, %2, %3;" : "=l"(d) : "l"(a), "l"(b), "l"(c));
    return d;
}

__global__ __launch_bounds__(GEMM_THREADS) void gemm_kernel(
    const float* __restrict__ b,
    float* __restrict__ out)
{
    extern __shared__ float smem[];
    float* As = smem;                       // [64][AS_STRIDE]
    float* Wt = smem + 64 * AS_STRIDE;      // [128][128] (k-major)
    float* bs = Wt + D * D;                 // [128]

    const int tid = threadIdx.x;
    const int rb  = blockIdx.x * 64;

    for (int i = tid; i < 64 * 32; i += GEMM_THREADS) {
        int r = i >> 5, c4 = i & 31;
        float4 v = make_float4(0.f, 0.f, 0.f, 0.f);
        int grow = rb + r;
        if (grow < N_NODES)
            v = *(const float4*)(g_agg + (size_t)grow * D + c4 * 4);
        *(float4*)(As + r * AS_STRIDE + c4 * 4) = v;
    }
    for (int i = tid; i < 128 * 32; i += GEMM_THREADS) {
        int k = i >> 5, c4 = i & 31;
        *(float4*)(Wt + k * D + c4 * 4) = *(const float4*)(g_Wt + k * D + c4 * 4);
    }
    if (tid < D) bs[tid] = b[tid];
    __syncthreads();

    const int tx = tid & 15, ty = tid >> 4;
    const int r0 = ty * 4;

    unsigned long long acc[4][4];
    {
        const unsigned long long* bp = (const unsigned long long*)bs;
        #pragma unroll
        for (int g = 0; g < 4; g++) {
            unsigned long long bv = bp[tx + 16 * g];
            #pragma unroll
            for (int i = 0; i < 4; i++) acc[i][g] = bv;
        }
    }

    #pragma unroll 8
    for (int k = 0; k < 128; k++) {
        const unsigned long long* wp = (const unsigned long long*)(Wt + k * D);
        unsigned long long w0 = wp[tx];
        unsigned long long w1 = wp[tx + 16];
        unsigned long long w2 = wp[tx + 32];
        unsigned long long w3 = wp[tx + 48];

        unsigned long long a2[4];
        #pragma unroll
        for (int i = 0; i < 4; i++)
            a2[i] = pack2(As[(r0 + i) * AS_STRIDE + k]);

        #pragma unroll
        for (int i = 0; i < 4; i++) {
            acc[i][0] = fma2(a2[i], w0, acc[i][0]);
            acc[i][1] = fma2(a2[i], w1, acc[i][1]);
            acc[i][2] = fma2(a2[i], w2, acc[i][2]);
            acc[i][3] = fma2(a2[i], w3, acc[i][3]);
        }
    }

    #pragma unroll
    for (int i = 0; i < 4; i++) {
        int grow = rb + r0 + i;
        if (grow < N_NODES) {
            unsigned long long* dst =
                (unsigned long long*)(out + (size_t)grow * D + 2 * tx);
            dst[0]  = acc[i][0];
            dst[16] = acc[i][1];
            dst[32] = acc[i][2];
            dst[48] = acc[i][3];
        }
    }
}

// ---------------------------------------------------------------------------
// Launch
// ---------------------------------------------------------------------------
extern "C" void kernel_launch(void* const* d_in, const int* in_sizes, int n_in,
                              void* d_out, int out_size) {
    const float* x   = (const float*)d_in[0];
    const void*  src = d_in[1];
    const void*  dst = d_in[2];
    const float* W   = (const float*)d_in[3];
    const float* b   = (const float*)d_in[4];
    float* out = (float*)d_out;

    const int gemm_smem = (64 * AS_STRIDE + D * D + D) * (int)sizeof(float);

    static int inited = 0;
    static void* deg_ptr = nullptr;
    if (!inited) {
        cudaFuncSetAttribute(gemm_kernel,
                             cudaFuncAttributeMaxDynamicSharedMemorySize,
                             gemm_smem);
        cudaGetSymbolAddress(&deg_ptr, g_deg);
        inited = 1;
    }

    const int scan_blocks = (N_NODES + SCAN_B - 1) / SCAN_B;  // 196

    detect_idx_kernel<<<1, 1>>>(src);
    prep_w_kernel<<<D, 128>>>(W);

    cudaMemsetAsync(deg_ptr, 0, N_NODES * sizeof(int));
    hist_kernel<<<(N_EDGES / 4 + 255) / 256, 256>>>(dst);
    scan1_kernel<<<scan_blocks, SCAN_B>>>();
    scan2_kernel<<<1, SCAN_B>>>(scan_blocks);
    scan3_kernel<<<(N_NODES + 255) / 256, 256>>>();
    fill_kernel<<<(N_EDGES / 4 + 255) / 256, 256>>>(src, dst);

    gather_kernel<<<(N_NODES + 7) / 8, 256>>>(x);

    gemm_kernel<<<GEMM_BLOCKS, GEMM_THREADS, gemm_smem>>>(b, out);
}